// round 7
// baseline (speedup 1.0000x reference)
#include <cuda_runtime.h>
#include <math.h>

#define BB   32
#define LL   4096
#define DIN  32
#define HH   256
#define NN   32
#define DOUT 16
#define J1   128   // H/2

// Scratch (device globals: allocation-free per harness rules)
__device__ float g_hrelu[BB*LL*J1];   // 64 MB
__device__ float g_kt[LL*HH];         // 4 MB: kt[m][h] = k[h][L-1-m] (+D[h] at m=L-1)
__device__ float g_part[BB*64*HH];    // 2 MB
__device__ float g_gel[BB*HH];        // gelu(y_last)
__device__ float g_glu[BB*HH];        // after GLU

// ---------------- kernel 1: hrelu = relu(data @ w1 + b1)  [R2 proven] ----------------
__global__ void __launch_bounds__(256) k_hrelu(const float* __restrict__ data,
                                               const float* __restrict__ w1,
                                               const float* __restrict__ b1) {
    __shared__ float sd[16][DIN];
    __shared__ float sw[DIN*J1];
    int tid = threadIdx.x;
    int row0 = blockIdx.x * 16;
    for (int u = tid; u < DIN*J1; u += 256) sw[u] = w1[u];
    for (int u = tid; u < 16*DIN; u += 256) {
        int r = u >> 5, i = u & 31;
        sd[r][i] = data[(size_t)(row0 + r)*DIN + i];
    }
    __syncthreads();
    int j  = tid & 127;
    int rr = tid >> 7;
    float bj = b1[j];
    #pragma unroll
    for (int r = rr; r < 16; r += 2) {
        float s = bj;
        #pragma unroll
        for (int i = 0; i < DIN; i++) s += sd[r][i] * sw[i*J1 + j];
        g_hrelu[(size_t)(row0 + r)*J1 + j] = fmaxf(s, 0.f);
    }
}

// ---------------- kernel 2: SSM kernel k, reversed+transposed  [R6, 16-wide chunks] --
__global__ void __launch_bounds__(256) k_kt(const float* __restrict__ log_dt,
                                            const float* __restrict__ A_re,
                                            const float* __restrict__ A_im,
                                            const float* __restrict__ C_re,
                                            const float* __restrict__ C_im,
                                            const float* __restrict__ Dv) {
    const int h  = threadIdx.x;
    const int l0 = blockIdx.x * 16;
    float acc[16];
    #pragma unroll
    for (int i = 0; i < 16; i++) acc[i] = 0.f;
    float dt = expf(log_dt[h]);
    for (int n = 0; n < NN; n++) {
        float are = A_re[h*NN+n], aim = A_im[h*NN+n];
        float dre = dt*are, dim = dt*aim;
        float er = expf(dre);
        float ws, wc; sincosf(dim, &ws, &wc);
        float wre = er*wc, wim = er*ws;                 // w = exp(dtA)
        float nre = wre - 1.f, nim = wim;
        float inv = 1.f/(are*are + aim*aim);
        float qre = (nre*are + nim*aim)*inv;
        float qim = (nim*are - nre*aim)*inv;
        float cre = C_re[h*NN+n], cim = C_im[h*NN+n];
        float kre = cre*qre - cim*qim;
        float kim = cre*qim + cim*qre;
        const double TWO_PI = 6.283185307179586476925286766559;
        double th = (double)dim * (double)l0;
        float thr = (float)(th - TWO_PI * rint(th * (1.0/TWO_PI)));
        float mag = expf(dre * (float)l0);
        float ps, pc; sincosf(thr, &ps, &pc);
        float pre = mag*pc, pim = mag*ps;
        #pragma unroll
        for (int i = 0; i < 16; i++) {
            acc[i] += kre*pre - kim*pim;
            float t = pre*wre - pim*wim;
            pim = pre*wim + pim*wre;
            pre = t;
        }
    }
    float dh = Dv[h];
    #pragma unroll
    for (int i = 0; i < 16; i++) {
        int l = l0 + i;
        float v = 2.f*acc[i];
        if (l == 0) v += dh;
        g_kt[(size_t)(LL-1-l)*HH + h] = v;
    }
}

// ---------------- kernel 3: fused hrelu@w2+b2 then dot with kt  [R2 proven] ----------
// 64(m) x 64(h) tile per block, 256 threads, 4x4 register tile (strided mapping).
__global__ void __launch_bounds__(256) k_gemm(const float* __restrict__ w2,
                                              const float* __restrict__ b2) {
    __shared__ float As[32][65];
    __shared__ float Ws[32][64];
    __shared__ float red[64*17];
    int tid = threadIdx.x;
    int tx = tid & 15, ty = tid >> 4;
    int row0 = blockIdx.x * 64;
    int h0   = blockIdx.y * 64;
    float acc[4][4];
    #pragma unroll
    for (int i = 0; i < 4; i++)
        #pragma unroll
        for (int j = 0; j < 4; j++) acc[i][j] = 0.f;

    for (int k0 = 0; k0 < J1; k0 += 32) {
        #pragma unroll
        for (int u = 0; u < 8; u++) {
            int idx = tid + u*256;
            int k = idx & 31, r = idx >> 5;
            As[k][r] = g_hrelu[(size_t)(row0 + r)*J1 + k0 + k];
        }
        #pragma unroll
        for (int u = 0; u < 8; u++) {
            int idx = tid + u*256;
            int hh = idx & 63, kk = idx >> 6;
            Ws[kk][hh] = w2[(size_t)(k0+kk)*HH + h0 + hh];
        }
        __syncthreads();
        #pragma unroll
        for (int kk = 0; kk < 32; kk++) {
            float a[4], w[4];
            #pragma unroll
            for (int i = 0; i < 4; i++) a[i] = As[kk][ty + i*16];
            #pragma unroll
            for (int j = 0; j < 4; j++) w[j] = Ws[kk][tx + j*16];
            #pragma unroll
            for (int i = 0; i < 4; i++)
                #pragma unroll
                for (int j = 0; j < 4; j++) acc[i][j] += a[i]*w[j];
        }
        __syncthreads();
    }
    // epilogue: x = acc + b2; multiply by kt; reduce m within block
    int b     = row0 >> 12;
    int mloc0 = row0 & 4095;
    float part[4] = {0.f, 0.f, 0.f, 0.f};
    #pragma unroll
    for (int j = 0; j < 4; j++) {
        int hcol = h0 + tx + j*16;
        float b2v = b2[hcol];
        #pragma unroll
        for (int i = 0; i < 4; i++) {
            int m = mloc0 + ty + i*16;
            float x = acc[i][j] + b2v;
            part[j] += x * g_kt[(size_t)m*HH + hcol];
        }
    }
    #pragma unroll
    for (int j = 0; j < 4; j++) red[(tx + j*16)*17 + ty] = part[j];
    __syncthreads();
    if (tid < 64) {
        float s = 0.f;
        #pragma unroll
        for (int q = 0; q < 16; q++) s += red[tid*17 + q];
        int mblk = blockIdx.x & 63;
        g_part[(size_t)(b*64 + mblk)*HH + h0 + tid] = s;
    }
}

// ---------------- kernel 4a: reduce partials + exact gelu ----------------
__global__ void __launch_bounds__(256) k_head_a() {
    int b = blockIdx.x, t = threadIdx.x;
    float y = 0.f;
    #pragma unroll 8
    for (int mb = 0; mb < 64; mb++) y += g_part[(size_t)(b*64 + mb)*HH + t];
    g_gel[b*HH + t] = 0.5f * y * (1.f + erff(y * 0.70710678118654752f));
}

// ---------------- kernel 4b: GLU: (g@Wg+bg) -> a*sigmoid(b) ----------------
__global__ void __launch_bounds__(128) k_head_b(const float* __restrict__ Wg,
                                                const float* __restrict__ bg) {
    __shared__ float gsh[HH];
    int b = blockIdx.x, t = blockIdx.y*128 + threadIdx.x;
    gsh[threadIdx.x]       = g_gel[b*HH + threadIdx.x];
    gsh[threadIdx.x + 128] = g_gel[b*HH + threadIdx.x + 128];
    __syncthreads();
    float a  = bg[t];
    float bs = bg[HH + t];
    #pragma unroll 8
    for (int h = 0; h < HH; h++) {
        float gv = gsh[h];
        a  += gv * Wg[(size_t)h*(2*HH) + t];
        bs += gv * Wg[(size_t)h*(2*HH) + HH + t];
    }
    g_glu[b*HH + t] = a / (1.f + expf(-bs));
}

// ---------------- kernel 4c: z = relu(glu@w3+b3); out = z@w4+b4 ----------------
__global__ void __launch_bounds__(128) k_head_c(const float* __restrict__ w3,
                                                const float* __restrict__ b3,
                                                const float* __restrict__ w4,
                                                const float* __restrict__ b4,
                                                float* __restrict__ out) {
    __shared__ float glu[HH];
    __shared__ float zsh[J1];
    int b = blockIdx.x, t = threadIdx.x;
    glu[t]       = g_glu[b*HH + t];
    glu[t + 128] = g_glu[b*HH + t + 128];
    __syncthreads();
    float z = b3[t];
    #pragma unroll 8
    for (int h = 0; h < HH; h++) z += glu[h] * w3[(size_t)h*J1 + t];
    zsh[t] = fmaxf(z, 0.f);
    __syncthreads();
    if (t < DOUT) {
        float o = b4[t];
        #pragma unroll 8
        for (int j = 0; j < J1; j++) o += zsh[j] * w4[j*DOUT + t];
        out[b*DOUT + t] = o;
    }
}

extern "C" void kernel_launch(void* const* d_in, const int* in_sizes, int n_in,
                              void* d_out, int out_size) {
    const float* data   = (const float*)d_in[0];
    const float* w1     = (const float*)d_in[1];
    const float* b1     = (const float*)d_in[2];
    const float* w2     = (const float*)d_in[3];
    const float* b2     = (const float*)d_in[4];
    const float* log_dt = (const float*)d_in[5];
    const float* A_re   = (const float*)d_in[6];
    const float* A_im   = (const float*)d_in[7];
    const float* C_re   = (const float*)d_in[8];
    const float* C_im   = (const float*)d_in[9];
    const float* Dv     = (const float*)d_in[10];
    const float* Wg     = (const float*)d_in[11];
    const float* bg     = (const float*)d_in[12];
    const float* w3     = (const float*)d_in[13];
    const float* b3     = (const float*)d_in[14];
    const float* w4     = (const float*)d_in[15];
    const float* b4     = (const float*)d_in[16];
    float* out = (float*)d_out;

    k_kt<<<LL/16, 256>>>(log_dt, A_re, A_im, C_re, C_im, Dv);
    k_hrelu<<<BB*LL/16, 256>>>(data, w1, b1);
    dim3 g3(BB*LL/64, HH/64);
    k_gemm<<<g3, 256>>>(w2, b2);
    k_head_a<<<BB, 256>>>();
    k_head_b<<<dim3(BB, 2), 128>>>(Wg, bg);
    k_head_c<<<BB, 128>>>(w3, b3, w4, b4, out);
}

// round 14
// speedup vs baseline: 2.3200x; 2.3200x over previous
#include <cuda_runtime.h>
#include <cuda_bf16.h>
#include <mma.h>
#include <math.h>
#include <stdint.h>

using namespace nvcuda;

#define BB   32
#define LL   4096
#define DIN  32
#define HH   256
#define NN   32
#define DOUT 16
#define J1   128   // H/2

// ---------------- scratch (device globals; allocation-free) ----------------
__device__ __nv_bfloat16 g_ah[BB*LL*J1];   // 32 MB: hrelu hi  [m][j]
__device__ __nv_bfloat16 g_al[BB*LL*J1];   // 32 MB: hrelu lo
__device__ __nv_bfloat16 g_w2h[J1*HH];     // w2 hi, natural [j][h]
__device__ __nv_bfloat16 g_w2l[J1*HH];     // w2 lo
__device__ float g_kt[LL*HH];              // kt[m][h] = k[h][L-1-m] (+D at m=L-1)
__device__ float g_part[BB*32*HH];         // per (b, m-tile of 128, h)
__device__ float g_gel[BB*HH];
__device__ float g_glu[BB*HH];

// ---------------- kernel 1: hrelu = relu(data@w1+b1) -> bf16 hi/lo ----------------
__global__ void __launch_bounds__(256) k_hrelu(const float* __restrict__ data,
                                               const float* __restrict__ w1,
                                               const float* __restrict__ b1) {
    __shared__ float sd[16][DIN];
    __shared__ float sw[DIN*J1];
    int tid = threadIdx.x;
    int row0 = blockIdx.x * 16;
    for (int u = tid; u < DIN*J1; u += 256) sw[u] = w1[u];
    for (int u = tid; u < 16*DIN; u += 256) {
        int r = u >> 5, i = u & 31;
        sd[r][i] = data[(size_t)(row0 + r)*DIN + i];
    }
    __syncthreads();
    int j  = tid & 127;
    int rr = tid >> 7;
    float bj = b1[j];
    #pragma unroll
    for (int r = rr; r < 16; r += 2) {
        float s = bj;
        #pragma unroll
        for (int i = 0; i < DIN; i++) s += sd[r][i] * sw[i*J1 + j];
        s = fmaxf(s, 0.f);
        __nv_bfloat16 hi = __float2bfloat16(s);
        __nv_bfloat16 lo = __float2bfloat16(s - __bfloat162float(hi));
        size_t o = (size_t)(row0 + r)*J1 + j;
        g_ah[o] = hi;
        g_al[o] = lo;
    }
}

// ---------------- kernel 1b: split w2 -> bf16 hi/lo (layout preserved [j][h]) ------
__global__ void __launch_bounds__(256) k_wsplit(const float* __restrict__ w2) {
    int gid = blockIdx.x*256 + threadIdx.x;   // 0 .. J1*HH-1
    float v = w2[gid];
    __nv_bfloat16 hi = __float2bfloat16(v);
    __nv_bfloat16 lo = __float2bfloat16(v - __bfloat162float(hi));
    g_w2h[gid] = hi;
    g_w2l[gid] = lo;
}

// ---------------- kernel 2: SSM kernel k, reversed+transposed ----------------
__global__ void __launch_bounds__(256) k_kt(const float* __restrict__ log_dt,
                                            const float* __restrict__ A_re,
                                            const float* __restrict__ A_im,
                                            const float* __restrict__ C_re,
                                            const float* __restrict__ C_im,
                                            const float* __restrict__ Dv) {
    const int h  = threadIdx.x;
    const int l0 = blockIdx.x * 16;
    float acc[16];
    #pragma unroll
    for (int i = 0; i < 16; i++) acc[i] = 0.f;
    float dt = expf(log_dt[h]);
    for (int n = 0; n < NN; n++) {
        float are = A_re[h*NN+n], aim = A_im[h*NN+n];
        float dre = dt*are, dim = dt*aim;
        float er = expf(dre);
        float ws, wc; sincosf(dim, &ws, &wc);
        float wre = er*wc, wim = er*ws;
        float nre = wre - 1.f, nim = wim;
        float inv = 1.f/(are*are + aim*aim);
        float qre = (nre*are + nim*aim)*inv;
        float qim = (nim*are - nre*aim)*inv;
        float cre = C_re[h*NN+n], cim = C_im[h*NN+n];
        float kre = cre*qre - cim*qim;
        float kim = cre*qim + cim*qre;
        const double TWO_PI = 6.283185307179586476925286766559;
        double th = (double)dim * (double)l0;
        float thr = (float)(th - TWO_PI * rint(th * (1.0/TWO_PI)));
        float mag = expf(dre * (float)l0);
        float ps, pc; sincosf(thr, &ps, &pc);
        float pre = mag*pc, pim = mag*ps;
        #pragma unroll
        for (int i = 0; i < 16; i++) {
            acc[i] += kre*pre - kim*pim;
            float t = pre*wre - pim*wim;
            pim = pre*wim + pim*wre;
            pre = t;
        }
    }
    float dh = Dv[h];
    #pragma unroll
    for (int i = 0; i < 16; i++) {
        int l = l0 + i;
        float v = 2.f*acc[i];
        if (l == 0) v += dh;
        g_kt[(size_t)(LL-1-l)*HH + h] = v;
    }
}

// ---------------- kernel 3: wmma bf16-split GEMM + kt epilogue ----------------
// CTA tile 128(m) x 128(h), grid (1024 m-tiles, 2 h-halves). 8 warps: 4(m) x 2(h),
// warp tile 32m x 64h = 2x4 frags of 16x16. K=128 in 8 chunks; per chunk 24 mma:
// AhBh + AhBl + AlBh (lo*lo dropped, ~2^-16 relative).
#define LDM 136
#define TILE_B (128*LDM*2)          // 34816 bytes per bf16 tile buffer
#define SM_AH 0
#define SM_AL (TILE_B)
#define SM_BH (2*TILE_B)
#define SM_BL (3*TILE_B)
#define SMEM_DYN (4*TILE_B)         // 139264

__global__ void __launch_bounds__(256) k_gemm_wmma(const float* __restrict__ b2) {
    extern __shared__ char smem[];
    int tid = threadIdx.x;
    int wid = tid >> 5;
    int row0 = blockIdx.x * 128;
    int h0   = blockIdx.y * 128;

    __nv_bfloat16* sAh = (__nv_bfloat16*)(smem + SM_AH);
    __nv_bfloat16* sAl = (__nv_bfloat16*)(smem + SM_AL);
    __nv_bfloat16* sBh = (__nv_bfloat16*)(smem + SM_BH);
    __nv_bfloat16* sBl = (__nv_bfloat16*)(smem + SM_BL);

    // ---- load A tiles: 128 rows x 128 bf16 = 2048 uint4 (16 uint4/row) ----
    {
        const uint4* srcH = (const uint4*)(&g_ah[(size_t)row0 * J1]);
        const uint4* srcL = (const uint4*)(&g_al[(size_t)row0 * J1]);
        #pragma unroll
        for (int t = 0; t < 8; t++) {
            int idx = tid + t*256;              // 0..2047
            int r = idx >> 4, q = idx & 15;     // 16 uint4 per 128-elem row
            *(uint4*)(&sAh[r*LDM + q*8]) = srcH[idx];
            *(uint4*)(&sAl[r*LDM + q*8]) = srcL[idx];
        }
    }
    // ---- load B tiles: w2[j][h0..h0+128), 128 rows x 128 bf16 = 2048 uint4 ----
    {
        #pragma unroll
        for (int t = 0; t < 8; t++) {
            int idx = tid + t*256;              // 0..2047
            int r = idx >> 4, q = idx & 15;
            *(uint4*)(&sBh[r*LDM + q*8]) = *(const uint4*)(&g_w2h[(size_t)r*HH + h0 + q*8]);
            *(uint4*)(&sBl[r*LDM + q*8]) = *(const uint4*)(&g_w2l[(size_t)r*HH + h0 + q*8]);
        }
    }
    __syncthreads();

    // ---- wmma mainloop ----
    int wm = wid & 3;     // m group (32 rows)
    int wn = wid >> 2;    // h group (64 cols)
    wmma::fragment<wmma::accumulator, 16, 16, 16, float> c[2][4];
    #pragma unroll
    for (int i = 0; i < 2; i++)
        #pragma unroll
        for (int j = 0; j < 4; j++) wmma::fill_fragment(c[i][j], 0.f);

    #pragma unroll
    for (int kk = 0; kk < 8; kk++) {
        wmma::fragment<wmma::matrix_a, 16, 16, 16, __nv_bfloat16, wmma::row_major> ah[2], al[2];
        #pragma unroll
        for (int i = 0; i < 2; i++) {
            int r = wm*32 + i*16;
            wmma::load_matrix_sync(ah[i], &sAh[r*LDM + kk*16], LDM);
            wmma::load_matrix_sync(al[i], &sAl[r*LDM + kk*16], LDM);
        }
        #pragma unroll
        for (int j = 0; j < 4; j++) {
            wmma::fragment<wmma::matrix_b, 16, 16, 16, __nv_bfloat16, wmma::row_major> bh, bl;
            int cb = wn*64 + j*16;
            wmma::load_matrix_sync(bh, &sBh[kk*16*LDM + cb], LDM);
            wmma::load_matrix_sync(bl, &sBl[kk*16*LDM + cb], LDM);
            #pragma unroll
            for (int i = 0; i < 2; i++) {
                wmma::mma_sync(c[i][j], ah[i], bh, c[i][j]);
                wmma::mma_sync(c[i][j], ah[i], bl, c[i][j]);
                wmma::mma_sync(c[i][j], al[i], bh, c[i][j]);
            }
        }
    }
    __syncthreads();   // done with A/B smem; alias as C

    // ---- store C to smem (fp32, 128 x LDM) ----
    float* Cs = (float*)smem;    // 128*136*4 = 69632 <= 2*TILE_B
    #pragma unroll
    for (int i = 0; i < 2; i++)
        #pragma unroll
        for (int j = 0; j < 4; j++)
            wmma::store_matrix_sync(&Cs[(wm*32 + i*16)*LDM + wn*64 + j*16],
                                    c[i][j], LDM, wmma::mem_row_major);
    __syncthreads();

    // ---- epilogue: (C + b2) * kt, reduce over 128 m ----
    __shared__ float red[128];
    int b     = row0 >> 12;
    int mloc0 = row0 & 4095;
    int h_loc = tid & 127;
    int mh    = tid >> 7;            // 0/1: which 64-m half
    int hg    = h0 + h_loc;
    float b2v = b2[hg];
    const float* ktp = &g_kt[(size_t)(mloc0 + mh*64)*HH + hg];
    float s = 0.f;
    #pragma unroll 8
    for (int mm = 0; mm < 64; mm++)
        s += (Cs[(mh*64 + mm)*LDM + h_loc] + b2v) * ktp[(size_t)mm*HH];
    if (mh == 1) red[h_loc] = s;
    __syncthreads();
    if (mh == 0) {
        float tot = s + red[h_loc];
        int tileInB = (row0 >> 7) & 31;
        g_part[((size_t)b*32 + tileInB)*HH + hg] = tot;
    }
}

// ---------------- kernel 4a: reduce partials + exact gelu ----------------
__global__ void __launch_bounds__(256) k_head_a() {
    int b = blockIdx.x, t = threadIdx.x;
    float y = 0.f;
    #pragma unroll 8
    for (int mb = 0; mb < 32; mb++) y += g_part[((size_t)b*32 + mb)*HH + t];
    g_gel[b*HH + t] = 0.5f * y * (1.f + erff(y * 0.70710678118654752f));
}

// ---------------- kernel 4b: GLU ----------------
__global__ void __launch_bounds__(128) k_head_b(const float* __restrict__ Wg,
                                                const float* __restrict__ bg) {
    __shared__ float gsh[HH];
    int b = blockIdx.x, t = blockIdx.y*128 + threadIdx.x;
    gsh[threadIdx.x]       = g_gel[b*HH + threadIdx.x];
    gsh[threadIdx.x + 128] = g_gel[b*HH + threadIdx.x + 128];
    __syncthreads();
    float a  = bg[t];
    float bs = bg[HH + t];
    #pragma unroll 8
    for (int h = 0; h < HH; h++) {
        float gv = gsh[h];
        a  += gv * Wg[(size_t)h*(2*HH) + t];
        bs += gv * Wg[(size_t)h*(2*HH) + HH + t];
    }
    g_glu[b*HH + t] = a / (1.f + expf(-bs));
}

// ---------------- kernel 4c: z = relu(glu@w3+b3); out = z@w4+b4 ----------------
__global__ void __launch_bounds__(128) k_head_c(const float* __restrict__ w3,
                                                const float* __restrict__ b3,
                                                const float* __restrict__ w4,
                                                const float* __restrict__ b4,
                                                float* __restrict__ out) {
    __shared__ float glu[HH];
    __shared__ float zsh[J1];
    int b = blockIdx.x, t = threadIdx.x;
    glu[t]       = g_glu[b*HH + t];
    glu[t + 128] = g_glu[b*HH + t + 128];
    __syncthreads();
    float z = b3[t];
    #pragma unroll 8
    for (int h = 0; h < HH; h++) z += glu[h] * w3[(size_t)h*J1 + t];
    zsh[t] = fmaxf(z, 0.f);
    __syncthreads();
    if (t < DOUT) {
        float o = b4[t];
        #pragma unroll 8
        for (int j = 0; j < J1; j++) o += zsh[j] * w4[j*DOUT + t];
        out[b*DOUT + t] = o;
    }
}

extern "C" void kernel_launch(void* const* d_in, const int* in_sizes, int n_in,
                              void* d_out, int out_size) {
    const float* data   = (const float*)d_in[0];
    const float* w1     = (const float*)d_in[1];
    const float* b1     = (const float*)d_in[2];
    const float* w2     = (const float*)d_in[3];
    const float* b2     = (const float*)d_in[4];
    const float* log_dt = (const float*)d_in[5];
    const float* A_re   = (const float*)d_in[6];
    const float* A_im   = (const float*)d_in[7];
    const float* C_re   = (const float*)d_in[8];
    const float* C_im   = (const float*)d_in[9];
    const float* Dv     = (const float*)d_in[10];
    const float* Wg     = (const float*)d_in[11];
    const float* bg     = (const float*)d_in[12];
    const float* w3     = (const float*)d_in[13];
    const float* b3     = (const float*)d_in[14];
    const float* w4     = (const float*)d_in[15];
    const float* b4     = (const float*)d_in[16];
    float* out = (float*)d_out;

    cudaFuncSetAttribute(k_gemm_wmma, cudaFuncAttributeMaxDynamicSharedMemorySize, SMEM_DYN);

    k_kt<<<LL/16, 256>>>(log_dt, A_re, A_im, C_re, C_im, Dv);
    k_hrelu<<<BB*LL/16, 256>>>(data, w1, b1);
    k_wsplit<<<J1*HH/256, 256>>>(w2);
    k_gemm_wmma<<<dim3(BB*LL/128, 2), 256, SMEM_DYN>>>(b2);
    k_head_a<<<BB, 256>>>();
    k_head_b<<<dim3(BB, 2), 128>>>(Wg, bg);
    k_head_c<<<BB, 128>>>(w3, b3, w4, b4, out);
}